// round 16
// baseline (speedup 1.0000x reference)
#include <cuda_runtime.h>
#include <cuda_fp16.h>
#include <cstdint>

#define RR 512
#define TT 4096
#define MM 16384
#define NNODE 2048
#define NCDF 8192
#define COFF (RR*TT)
#define YOFF (COFF + MM*TT)     /* 69206016 */

#define MEXT 18432              /* 16384 movements + 2048 node rows */
#define BM 128
#define BN 128
#define BK 64
#define NIT (RR/BK)             /* 8 */
#define SROW 72                 /* smem halves per row (64 + 8 pad) */
#define BUFH ((BM + BN) * SROW) /* halves per pipeline stage: 18432 */

// ---------------- scratch (device globals; no allocation) ----------------
__device__ __align__(16) __half g_Aext[MEXT * RR];    // 18.9 MB
__device__ __align__(16) __half g_Xt[TT * RR];        // 4 MB
__device__ float g_w[NNODE];                          // per-node quartic weight

// ---------------- PTX helpers ----------------
__device__ __forceinline__ unsigned smem_u32(const void* p) {
    return (unsigned)__cvta_generic_to_shared(p);
}
#define CP_ASYNC16(dst, src) \
    asm volatile("cp.async.cg.shared.global [%0], [%1], 16;" :: "r"(dst), "l"(src))
#define CP_COMMIT() asm volatile("cp.async.commit_group;")
#define CP_WAIT(n)  asm volatile("cp.async.wait_group %0;" :: "n"(n))

#define LDSM_X4(r, addr) \
    asm volatile("ldmatrix.sync.aligned.m8n8.x4.shared.b16 {%0,%1,%2,%3}, [%4];" \
        : "=r"((r)[0]), "=r"((r)[1]), "=r"((r)[2]), "=r"((r)[3]) : "r"(addr))

#define MMA16816(c, a, b0, b1) \
    asm volatile("mma.sync.aligned.m16n8k16.row.col.f32.f16.f16.f32 " \
        "{%0,%1,%2,%3}, {%4,%5,%6,%7}, {%8,%9}, {%0,%1,%2,%3};" \
        : "+f"((c)[0]), "+f"((c)[1]), "+f"((c)[2]), "+f"((c)[3]) \
        : "r"((a)[0]), "r"((a)[1]), "r"((a)[2]), "r"((a)[3]), "r"(b0), "r"(b1))

// ---- 0: BPR constants: w[n] = sum co4; y[t] = base (runs BEFORE gemm) ----
// y_t = base + sum_n w[n]*flow[n,t]^4 (clip(.,1e-6) drop validated in R15)
__global__ void k_prep(const float* __restrict__ tf, const float* __restrict__ cap,
                       const float* __restrict__ radio,
                       const int* __restrict__ cdfn, float* __restrict__ outp) {
    __shared__ float red[1024];
    int tid = threadIdx.x;
    float local = 0.f;
    for (int c = tid; c < NCDF; c += 1024) {
        float tfr = tf[c] * radio[c];
        float ic = 1.f / cap[c];
        float ic2 = ic * ic;
        atomicAdd(&g_w[cdfn[c]], 0.15f * tfr * ic2 * ic2);
        local += tfr;
    }
    red[tid] = local;
    __syncthreads();
    for (int s = 512; s > 0; s >>= 1) {
        if (tid < s) red[tid] += red[tid + s];
        __syncthreads();
    }
    float base = red[0];
    for (int t = tid; t < TT; t += 1024) outp[YOFF + t] = base;
}

// ---- 1: relu(x_raw) -> fp32 out x-region AND fp16 Xt[t][k] (fused) ----
__global__ void k_prepXt(const float* __restrict__ xr, float* __restrict__ out) {
    __shared__ float st[64][129];
    int ti = blockIdx.x, kc = blockIdx.y, tid = threadIdx.x;   // 256 thr
    for (int i = tid; i < 64 * 128; i += 256) {
        int k = i >> 7, t = i & 127;
        st[k][t] = fmaxf(xr[(size_t)(kc * 64 + k) * TT + ti * 128 + t], 0.f);
    }
    __syncthreads();
    for (int i = tid; i < 64 * 128; i += 256) {
        int k = i >> 7, t = i & 127;
        out[(size_t)(kc * 64 + k) * TT + ti * 128 + t] = st[k][t];
    }
    for (int i = tid; i < 128 * 32; i += 256) {
        int t = i >> 5, kp = (i & 31) * 2;
        __half2 h = __floats2half2_rn(st[kp][t], st[kp + 1][t]);
        *(__half2*)(g_Xt + (size_t)(ti * 128 + t) * RR + kc * 64 + kp) = h;
    }
}

// ---- 2: A -> fp16 rows of g_Aext; node rows built IN-PLACE via half2 atomics
// (counts are small integers -> exact in fp16, order-independent)
__global__ void k_prepA_acc(const float* __restrict__ A,
                            const int* __restrict__ mnode) {
    int idx = blockIdx.x * 256 + threadIdx.x;    // one float4 of A
    int m = idx >> 7, c4 = idx & 127;
    float4 v = ((const float4*)A)[idx];
    int r = c4 * 4;
    __half2 h0 = __floats2half2_rn(v.x, v.y);
    __half2 h1 = __floats2half2_rn(v.z, v.w);
    *(__half2*)(g_Aext + (size_t)m * RR + r)     = h0;
    *(__half2*)(g_Aext + (size_t)m * RR + r + 2) = h1;
    int node = mnode[m];
    __half2* bn = (__half2*)(g_Aext + (size_t)(MM + node) * RR + r);
    if (v.x > 0.5f || v.y > 0.5f) atomicAdd(bn,     h0);
    if (v.z > 0.5f || v.w > 0.5f) atomicAdd(bn + 1, h1);
}

// ---- 3: HMMA GEMM: D[i,t] = Aext[i,:] @ x[:,t].
// Movement tiles (m0 < MM): store c_pred. Node tiles: reduce w*flow^4
// straight out of the accumulators into y via smem + atomics (no gmem flow).
__global__ void __launch_bounds__(256, 2) k_gemm_mma(float* __restrict__ outp) {
    extern __shared__ __align__(16) __half sm[];
    int tid = threadIdx.x, lane = tid & 31, w = tid >> 5;
    int wm = w >> 2, wn = w & 3;
    int t0 = blockIdx.x * BN, m0 = blockIdx.y * BM;

#define SA(buf) (sm + (buf) * BUFH)
#define SX(buf) (sm + (buf) * BUFH + BM * SROW)
#define LOADT(buf, kb) do {                                                   \
    const __half* _gA = g_Aext + (size_t)m0 * RR + (kb) * BK;                 \
    const __half* _gX = g_Xt  + (size_t)t0 * RR + (kb) * BK;                  \
    __half* _sa = SA(buf);                                                    \
    __half* _sx = SX(buf);                                                    \
    _Pragma("unroll")                                                         \
    for (int _q = 0; _q < 4; ++_q) {                                          \
        int _idx = tid + _q * 256;                                            \
        int _r = _idx >> 3, _ch = _idx & 7;                                   \
        CP_ASYNC16(smem_u32(_sa + _r * SROW + _ch * 8),                       \
                   _gA + (size_t)_r * RR + _ch * 8);                          \
    }                                                                         \
    _Pragma("unroll")                                                         \
    for (int _q = 0; _q < 4; ++_q) {                                          \
        int _idx = tid + _q * 256;                                            \
        int _r = _idx >> 3, _ch = _idx & 7;                                   \
        CP_ASYNC16(smem_u32(_sx + _r * SROW + _ch * 8),                       \
                   _gX + (size_t)_r * RR + _ch * 8);                          \
    }                                                                         \
} while (0)

    LOADT(0, 0); CP_COMMIT();
    LOADT(1, 1); CP_COMMIT();

    float acc[4][4][4];
    #pragma unroll
    for (int a = 0; a < 4; ++a)
        #pragma unroll
        for (int b = 0; b < 4; ++b)
            #pragma unroll
            for (int c = 0; c < 4; ++c) acc[a][b][c] = 0.f;

    // ldmatrix lane geometry (validated in R12)
    int a_row = wm * 64 + (lane & 15);
    int a_kh  = (lane >> 4) * 8;
    int b_row = wn * 32 + (((lane >> 4) & 1) << 3) + (lane & 7);
    int b_kh  = ((lane >> 3) & 1) * 8;

    int buf = 0, nbuf = 2;
    for (int it = 0; it < NIT; ++it) {
        CP_WAIT(1);
        __syncthreads();
        if (it + 2 < NIT) LOADT(nbuf, it + 2);
        CP_COMMIT();
        const __half* A_ = SA(buf);
        const __half* X_ = SX(buf);
        #pragma unroll
        for (int kk = 0; kk < BK; kk += 16) {
            uint32_t af[4][4], bf[2][4];
            #pragma unroll
            for (int mi = 0; mi < 4; ++mi) {
                unsigned ad = smem_u32(A_ + (a_row + mi * 16) * SROW + kk + a_kh);
                LDSM_X4(af[mi], ad);
            }
            #pragma unroll
            for (int nb = 0; nb < 2; ++nb) {
                unsigned bd = smem_u32(X_ + (b_row + nb * 16) * SROW + kk + b_kh);
                LDSM_X4(bf[nb], bd);
            }
            #pragma unroll
            for (int mi = 0; mi < 4; ++mi)
                #pragma unroll
                for (int ni = 0; ni < 4; ++ni)
                    MMA16816(acc[mi][ni], af[mi],
                             bf[ni >> 1][(ni & 1) * 2], bf[ni >> 1][(ni & 1) * 2 + 1]);
        }
        buf = (buf == 2) ? 0 : buf + 1;
        nbuf = (nbuf == 2) ? 0 : nbuf + 1;
    }

    int i_base = wm * 64 + (lane >> 2);
    if (m0 < MM) {
        // c_pred epilogue: direct v2 stores
        float* base = outp + COFF + (size_t)m0 * TT;
        int t_base = t0 + wn * 32 + (lane & 3) * 2;
        #pragma unroll
        for (int mi = 0; mi < 4; ++mi)
            #pragma unroll
            for (int ni = 0; ni < 4; ++ni) {
                int i = i_base + mi * 16;
                int t = t_base + ni * 8;
                *(float2*)&base[(size_t)i * TT + t] =
                    make_float2(acc[mi][ni][0], acc[mi][ni][1]);
                *(float2*)&base[(size_t)(i + 8) * TT + t] =
                    make_float2(acc[mi][ni][2], acc[mi][ni][3]);
            }
    } else {
        // node tile: y[t] += sum_n w[n]*flow^4, flow straight from accums
        __syncthreads();                      // all warps done reading smem
        float* ys = (float*)sm;               // [BN] f32
        for (int i = tid; i < BN; i += 256) ys[i] = 0.f;
        __syncthreads();
        int nb0 = m0 - MM + i_base;
        int tl0 = wn * 32 + (lane & 3) * 2;
        #pragma unroll
        for (int mi = 0; mi < 4; ++mi) {
            float w0 = __ldg(&g_w[nb0 + mi * 16]);
            float w1 = __ldg(&g_w[nb0 + mi * 16 + 8]);
            #pragma unroll
            for (int ni = 0; ni < 4; ++ni) {
                int tl = tl0 + ni * 8;
                float f0 = acc[mi][ni][0], f1 = acc[mi][ni][1];
                float f2 = acc[mi][ni][2], f3 = acc[mi][ni][3];
                float q0 = (f0 * f0) * (f0 * f0);
                float q1 = (f1 * f1) * (f1 * f1);
                float q2 = (f2 * f2) * (f2 * f2);
                float q3 = (f3 * f3) * (f3 * f3);
                atomicAdd(&ys[tl],     w0 * q0 + w1 * q2);
                atomicAdd(&ys[tl + 1], w0 * q1 + w1 * q3);
            }
        }
        __syncthreads();
        if (tid < BN) atomicAdd(&outp[YOFF + t0 + tid], ys[tid]);
    }
#undef LOADT
#undef SA
#undef SX
}

// ---------------- launch ----------------
extern "C" void kernel_launch(void* const* d_in, const int* in_sizes, int n_in,
                              void* d_out, int out_size) {
    const float* x_raw  = (const float*)d_in[0];
    const float* A      = (const float*)d_in[1];
    const float* t_free = (const float*)d_in[2];
    const float* cap    = (const float*)d_in[3];
    const float* radio  = (const float*)d_in[4];
    const int*   mnode  = (const int*)d_in[5];
    const int*   cdfn   = (const int*)d_in[6];
    float* out = (float*)d_out;

    const int gemm_smem = 3 * BUFH * 2;               // 110592 B (3 stages)
    static void* w_ptr = nullptr;
    static void* aext_ptr = nullptr;
    if (!w_ptr) {
        cudaFuncSetAttribute(k_gemm_mma,
                             cudaFuncAttributeMaxDynamicSharedMemorySize, gemm_smem);
        cudaGetSymbolAddress(&w_ptr, g_w);
        cudaGetSymbolAddress(&aext_ptr, g_Aext);
    }

    cudaMemsetAsync(w_ptr, 0, (size_t)NNODE * 4, 0);
    // zero the node-row (Bn) region of Aext — rebuilt by half2 atomics each call
    cudaMemsetAsync((char*)aext_ptr + (size_t)MM * RR * 2, 0,
                    (size_t)NNODE * RR * 2, 0);

    k_prep<<<1, 1024>>>(t_free, cap, radio, cdfn, out);   // 0 (w, base, y init)
    dim3 gx(TT / 128, RR / 64);                           // 32 x 8
    k_prepXt<<<gx, 256>>>(x_raw, out);                    // 1 (fused relu)
    k_prepA_acc<<<MM * (RR / 4) / 256, 256>>>(A, mnode);  // 2 (Aext + Bn)

    dim3 gg(TT / BN, MEXT / BM);                          // 32 x 144
    k_gemm_mma<<<gg, 256, gemm_smem>>>(out);              // 3 (ncu capture slot)
}

// round 17
// speedup vs baseline: 1.0975x; 1.0975x over previous
#include <cuda_runtime.h>
#include <cuda_fp16.h>
#include <cstdint>

#define RR 512
#define TT 4096
#define MM 16384
#define NNODE 2048
#define NCDF 8192
#define COFF (RR*TT)
#define YOFF (COFF + MM*TT)     /* 69206016 */

#define MEXT 18432              /* 16384 movements + 2048 node rows */
#define BM 128
#define BN 128
#define BK 64
#define NIT (RR/BK)             /* 8 */
#define SROW 72                 /* smem halves per row (64 + 8 pad) */
#define BUFH ((BM + BN) * SROW) /* halves per pipeline stage: 18432 */

// ---------------- scratch (device globals; no allocation) ----------------
__device__ __align__(16) __half g_Aext[MEXT * RR];    // 18.9 MB
__device__ __align__(16) __half g_Xt[TT * RR];        // 4 MB
__device__ float g_node_flow[NNODE * TT];             // 32 MB
__device__ float g_w[NNODE];                          // per-node quartic weight

// ---------------- PTX helpers ----------------
__device__ __forceinline__ unsigned smem_u32(const void* p) {
    return (unsigned)__cvta_generic_to_shared(p);
}
#define CP_ASYNC16(dst, src) \
    asm volatile("cp.async.cg.shared.global [%0], [%1], 16;" :: "r"(dst), "l"(src))
#define CP_COMMIT() asm volatile("cp.async.commit_group;")
#define CP_WAIT(n)  asm volatile("cp.async.wait_group %0;" :: "n"(n))

#define LDSM_X4(r, addr) \
    asm volatile("ldmatrix.sync.aligned.m8n8.x4.shared.b16 {%0,%1,%2,%3}, [%4];" \
        : "=r"((r)[0]), "=r"((r)[1]), "=r"((r)[2]), "=r"((r)[3]) : "r"(addr))

#define MMA16816(c, a, b0, b1) \
    asm volatile("mma.sync.aligned.m16n8k16.row.col.f32.f16.f16.f32 " \
        "{%0,%1,%2,%3}, {%4,%5,%6,%7}, {%8,%9}, {%0,%1,%2,%3};" \
        : "+f"((c)[0]), "+f"((c)[1]), "+f"((c)[2]), "+f"((c)[3]) \
        : "r"((a)[0]), "r"((a)[1]), "r"((a)[2]), "r"((a)[3]), "r"(b0), "r"(b1))

// ---- 0: relu(x_raw) -> fp32 out x-region AND fp16 Xt[t][k] (fused) ----
__global__ void k_prepXt(const float* __restrict__ xr, float* __restrict__ out) {
    __shared__ float st[64][129];
    int ti = blockIdx.x, kc = blockIdx.y, tid = threadIdx.x;   // 256 thr
    for (int i = tid; i < 64 * 128; i += 256) {
        int k = i >> 7, t = i & 127;
        st[k][t] = fmaxf(xr[(size_t)(kc * 64 + k) * TT + ti * 128 + t], 0.f);
    }
    __syncthreads();
    for (int i = tid; i < 64 * 128; i += 256) {
        int k = i >> 7, t = i & 127;
        out[(size_t)(kc * 64 + k) * TT + ti * 128 + t] = st[k][t];
    }
    for (int i = tid; i < 128 * 32; i += 256) {
        int t = i >> 5, kp = (i & 31) * 2;
        __half2 h = __floats2half2_rn(st[kp][t], st[kp + 1][t]);
        *(__half2*)(g_Xt + (size_t)(ti * 128 + t) * RR + kc * 64 + kp) = h;
    }
}

// ---- 1: A -> fp16 rows of g_Aext; node rows built IN-PLACE via half2 atomics
// (counts are small integers -> exact in fp16, order-independent)
__global__ void k_prepA_acc(const float* __restrict__ A,
                            const int* __restrict__ mnode) {
    int idx = blockIdx.x * 256 + threadIdx.x;    // one float4 of A
    int m = idx >> 7, c4 = idx & 127;
    float4 v = ((const float4*)A)[idx];
    int r = c4 * 4;
    __half2 h0 = __floats2half2_rn(v.x, v.y);
    __half2 h1 = __floats2half2_rn(v.z, v.w);
    *(__half2*)(g_Aext + (size_t)m * RR + r)     = h0;
    *(__half2*)(g_Aext + (size_t)m * RR + r + 2) = h1;
    int node = mnode[m];
    __half2* bn = (__half2*)(g_Aext + (size_t)(MM + node) * RR + r);
    if (v.x > 0.5f || v.y > 0.5f) atomicAdd(bn,     h0);
    if (v.z > 0.5f || v.w > 0.5f) atomicAdd(bn + 1, h1);
}

// ---- 2: BPR constants: w[n] = sum co4; base reduction; y[t] = base ----
__global__ void k_prep(const float* __restrict__ tf, const float* __restrict__ cap,
                       const float* __restrict__ radio,
                       const int* __restrict__ cdfn, float* __restrict__ outp) {
    __shared__ float red[1024];
    int tid = threadIdx.x;
    float local = 0.f;
    for (int c = tid; c < NCDF; c += 1024) {
        float tfr = tf[c] * radio[c];
        float ic = 1.f / cap[c];
        float ic2 = ic * ic;
        atomicAdd(&g_w[cdfn[c]], 0.15f * tfr * ic2 * ic2);
        local += tfr;
    }
    red[tid] = local;
    __syncthreads();
    for (int s = 512; s > 0; s >>= 1) {
        if (tid < s) red[tid] += red[tid + s];
        __syncthreads();
    }
    float base = red[0];
    for (int t = tid; t < TT; t += 1024) outp[YOFF + t] = base;
}

// ---- 3: HMMA GEMM (EXACT R15 body): D[i,t] = Aext[i,:] @ x[:,t]
// rows >= 16384 stream to g_node_flow. 256 thr, 128x128 tile, BK=64,
// triple-buffered cp.async, one __syncthreads per iteration.
__global__ void __launch_bounds__(256, 2) k_gemm_mma(float* __restrict__ outp) {
    extern __shared__ __align__(16) __half sm[];
    int tid = threadIdx.x, lane = tid & 31, w = tid >> 5;
    int wm = w >> 2, wn = w & 3;
    int t0 = blockIdx.x * BN, m0 = blockIdx.y * BM;

#define SA(buf) (sm + (buf) * BUFH)
#define SX(buf) (sm + (buf) * BUFH + BM * SROW)
#define LOADT(buf, kb) do {                                                   \
    const __half* _gA = g_Aext + (size_t)m0 * RR + (kb) * BK;                 \
    const __half* _gX = g_Xt  + (size_t)t0 * RR + (kb) * BK;                  \
    __half* _sa = SA(buf);                                                    \
    __half* _sx = SX(buf);                                                    \
    _Pragma("unroll")                                                         \
    for (int _q = 0; _q < 4; ++_q) {                                          \
        int _idx = tid + _q * 256;                                            \
        int _r = _idx >> 3, _ch = _idx & 7;                                   \
        CP_ASYNC16(smem_u32(_sa + _r * SROW + _ch * 8),                       \
                   _gA + (size_t)_r * RR + _ch * 8);                          \
    }                                                                         \
    _Pragma("unroll")                                                         \
    for (int _q = 0; _q < 4; ++_q) {                                          \
        int _idx = tid + _q * 256;                                            \
        int _r = _idx >> 3, _ch = _idx & 7;                                   \
        CP_ASYNC16(smem_u32(_sx + _r * SROW + _ch * 8),                       \
                   _gX + (size_t)_r * RR + _ch * 8);                          \
    }                                                                         \
} while (0)

    LOADT(0, 0); CP_COMMIT();
    LOADT(1, 1); CP_COMMIT();

    float acc[4][4][4];
    #pragma unroll
    for (int a = 0; a < 4; ++a)
        #pragma unroll
        for (int b = 0; b < 4; ++b)
            #pragma unroll
            for (int c = 0; c < 4; ++c) acc[a][b][c] = 0.f;

    // ldmatrix lane geometry (validated in R12)
    int a_row = wm * 64 + (lane & 15);
    int a_kh  = (lane >> 4) * 8;
    int b_row = wn * 32 + (((lane >> 4) & 1) << 3) + (lane & 7);
    int b_kh  = ((lane >> 3) & 1) * 8;

    int buf = 0, nbuf = 2;
    for (int it = 0; it < NIT; ++it) {
        CP_WAIT(1);
        __syncthreads();
        if (it + 2 < NIT) LOADT(nbuf, it + 2);
        CP_COMMIT();
        const __half* A_ = SA(buf);
        const __half* X_ = SX(buf);
        #pragma unroll
        for (int kk = 0; kk < BK; kk += 16) {
            uint32_t af[4][4], bf[2][4];
            #pragma unroll
            for (int mi = 0; mi < 4; ++mi) {
                unsigned ad = smem_u32(A_ + (a_row + mi * 16) * SROW + kk + a_kh);
                LDSM_X4(af[mi], ad);
            }
            #pragma unroll
            for (int nb = 0; nb < 2; ++nb) {
                unsigned bd = smem_u32(X_ + (b_row + nb * 16) * SROW + kk + b_kh);
                LDSM_X4(bf[nb], bd);
            }
            #pragma unroll
            for (int mi = 0; mi < 4; ++mi)
                #pragma unroll
                for (int ni = 0; ni < 4; ++ni)
                    MMA16816(acc[mi][ni], af[mi],
                             bf[ni >> 1][(ni & 1) * 2], bf[ni >> 1][(ni & 1) * 2 + 1]);
        }
        buf = (buf == 2) ? 0 : buf + 1;
        nbuf = (nbuf == 2) ? 0 : nbuf + 1;
    }

    // epilogue: direct v2 stores (full 32B sectors per i-row)
    float* base = (m0 >= MM) ? (g_node_flow + (size_t)(m0 - MM) * TT)
                             : (outp + COFF + (size_t)m0 * TT);
    int i_base = wm * 64 + (lane >> 2);
    int t_base = t0 + wn * 32 + (lane & 3) * 2;
    #pragma unroll
    for (int mi = 0; mi < 4; ++mi)
        #pragma unroll
        for (int ni = 0; ni < 4; ++ni) {
            int i = i_base + mi * 16;
            int t = t_base + ni * 8;
            *(float2*)&base[(size_t)i * TT + t] =
                make_float2(acc[mi][ni][0], acc[mi][ni][1]);
            *(float2*)&base[(size_t)(i + 8) * TT + t] =
                make_float2(acc[mi][ni][2], acc[mi][ni][3]);
        }
#undef LOADT
#undef SA
#undef SX
}

// ---- 4: y += sum_n w[n]*flow^4, node-chunked with atomics ----
__global__ void k_y2(float* __restrict__ outp) {
    int t = blockIdx.x * blockDim.x + threadIdx.x;   // 8 x 512 = 4096
    int n0 = blockIdx.y * 64;
    float s = 0.f;
    #pragma unroll 4
    for (int n = n0; n < n0 + 64; ++n) {
        float wv = __ldg(&g_w[n]);
        float f = g_node_flow[(size_t)n * TT + t];
        float f2 = f * f;
        s += wv * f2 * f2;
    }
    atomicAdd(&outp[YOFF + t], s);
}

// ---------------- launch ----------------
extern "C" void kernel_launch(void* const* d_in, const int* in_sizes, int n_in,
                              void* d_out, int out_size) {
    const float* x_raw  = (const float*)d_in[0];
    const float* A      = (const float*)d_in[1];
    const float* t_free = (const float*)d_in[2];
    const float* cap    = (const float*)d_in[3];
    const float* radio  = (const float*)d_in[4];
    const int*   mnode  = (const int*)d_in[5];
    const int*   cdfn   = (const int*)d_in[6];
    float* out = (float*)d_out;

    const int gemm_smem = 3 * BUFH * 2;               // 110592 B (3 stages)
    static void* w_ptr = nullptr;
    static void* aext_ptr = nullptr;
    if (!w_ptr) {
        cudaFuncSetAttribute(k_gemm_mma,
                             cudaFuncAttributeMaxDynamicSharedMemorySize, gemm_smem);
        cudaGetSymbolAddress(&w_ptr, g_w);
        cudaGetSymbolAddress(&aext_ptr, g_Aext);
    }

    cudaMemsetAsync(w_ptr, 0, (size_t)NNODE * 4, 0);
    // zero the node-row (Bn) region of Aext — rebuilt by half2 atomics each call
    cudaMemsetAsync((char*)aext_ptr + (size_t)MM * RR * 2, 0,
                    (size_t)NNODE * RR * 2, 0);

    dim3 gx(TT / 128, RR / 64);                           // 32 x 8
    k_prepXt<<<gx, 256>>>(x_raw, out);                    // 0 (fused relu)
    k_prepA_acc<<<MM * (RR / 4) / 256, 256>>>(A, mnode);  // 1 (Aext + Bn)
    k_prep<<<1, 1024>>>(t_free, cap, radio, cdfn, out);   // 2 (w, base, y=base)

    dim3 gg(TT / BN, MEXT / BM);                          // 32 x 144
    k_gemm_mma<<<gg, 256, gemm_smem>>>(out);              // 3 (ncu capture slot)

    dim3 gy(TT / 512, NNODE / 64);                        // 8 x 32
    k_y2<<<gy, 512>>>(out);                               // 4
}